// round 13
// baseline (speedup 1.0000x reference)
#include <cuda_runtime.h>

// Fixed problem shape
#define BB   4
#define CC   256
#define HH   128
#define WW   256
#define NGRP 4
#define CG   64      // channels per group
#define WIN  9       // window taps (1 x 9)
#define CK   16      // channels per pipeline chunk
#define NCH  (CC / CK)   // 16 chunks; 4 chunks per group
#define SRS  264     // padded smem row: pixel w at col w+4, replicate pad 4 each side

__shared__ float sA[CK][SRS];
__shared__ float sB[CK][SRS];

__device__ __forceinline__
void gather16(float (&buf)[CK][SRS], const float* __restrict__ rbase,
              int ch0, int w, int HW,
              int o00, int o01, int o10, int o11,
              float w00, float w01, float w10, float w11)
{
#pragma unroll
    for (int cc = 0; cc < CK; ++cc) {
        const float* rb = rbase + (size_t)(ch0 + cc) * HW;
        float v = rb[o00] * w00;
        v = fmaf(rb[o01], w01, v);
        v = fmaf(rb[o10], w10, v);
        v = fmaf(rb[o11], w11, v);
        buf[cc][4 + w] = v;
        if (w == 0) {
            buf[cc][0] = v; buf[cc][1] = v; buf[cc][2] = v; buf[cc][3] = v;
        }
        if (w == WW - 1) {
            buf[cc][WW + 4] = v; buf[cc][WW + 5] = v;
            buf[cc][WW + 6] = v; buf[cc][WW + 7] = v;
        }
    }
}

__device__ __forceinline__
void consume16(const float (&buf)[CK][SRS], const float* __restrict__ lbase,
               int ch0, int w, int HW, float (&acc)[WIN])
{
#pragma unroll
    for (int cc = 0; cc < CK; ++cc) {
        const float lv = lbase[(size_t)(ch0 + cc) * HW];
        const float* sp = &buf[cc][w];
#pragma unroll
        for (int k = 0; k < WIN; ++k)
            acc[k] = fmaf(lv, sp[k], acc[k]);
    }
}

__global__ __launch_bounds__(256, 3)
void crestereo_pipe_kernel(const float* __restrict__ left,
                           const float* __restrict__ right,
                           const float* __restrict__ flow,
                           float* __restrict__ out)
{
    const int bh = blockIdx.x;
    const int b  = bh >> 7;          // bh / HH
    const int h  = bh & (HH - 1);
    const int w  = threadIdx.x;
    const int HW = HH * WW;

    // ---- per-pixel bilinear setup (invariant across channels) ----
    const float fx = flow[(((size_t)b * 2 + 0) * HH + h) * WW + w];
    const float fy = flow[(((size_t)b * 2 + 1) * HH + h) * WW + w];
    const float x = (float)w + fx;
    const float y = (float)h + fy;
    const float x0f = floorf(x);
    const float y0f = floorf(y);
    const int ix0 = (int)x0f;
    const int iy0 = (int)y0f;
    const float ax = x - x0f;
    const float ay = y - y0f;

    float w00 = (1.f - ax) * (1.f - ay);
    float w01 = ax * (1.f - ay);
    float w10 = (1.f - ax) * ay;
    float w11 = ax * ay;

    const bool vx0 = (ix0     >= 0) & (ix0     <= WW - 1);
    const bool vx1 = (ix0 + 1 >= 0) & (ix0 + 1 <= WW - 1);
    const bool vy0 = (iy0     >= 0) & (iy0     <= HH - 1);
    const bool vy1 = (iy0 + 1 >= 0) & (iy0 + 1 <= HH - 1);
    if (!(vx0 & vy0)) w00 = 0.f;
    if (!(vx1 & vy0)) w01 = 0.f;
    if (!(vx0 & vy1)) w10 = 0.f;
    if (!(vx1 & vy1)) w11 = 0.f;

    const int x0c = min(max(ix0, 0), WW - 1);
    const int x1c = min(max(ix0 + 1, 0), WW - 1);
    const int y0c = min(max(iy0, 0), HH - 1);
    const int y1c = min(max(iy0 + 1, 0), HH - 1);

    const int o00 = y0c * WW + x0c;
    const int o01 = y0c * WW + x1c;
    const int o10 = y1c * WW + x0c;
    const int o11 = y1c * WW + x1c;

    const float* lbase = left  + (size_t)b * CC * HW + (size_t)h * WW + w;
    const float* rbase = right + (size_t)b * CC * HW;
    const float scale = 1.f / (float)CG;

    float acc[WIN];
#pragma unroll
    for (int k = 0; k < WIN; ++k) acc[k] = 0.f;

    // ---- prologue: fill A with chunk 0 ----
    gather16(sA, rbase, 0, w, HW, o00, o01, o10, o11, w00, w01, w10, w11);

    // ---- pipelined mainloop: 16 segments, one sync each, unrolled x2 for
    //      compile-time buffer identity (no pointer selection => no aliasing) ----
#pragma unroll 1
    for (int cp = 0; cp < NCH / 2; ++cp) {
        const int c0 = 2 * cp;       // even chunk -> consume A, gather B
        const int c1 = c0 + 1;       // odd  chunk -> consume B, gather A

        // segment c0
        __syncthreads();
        consume16(sA, lbase, c0 * CK, w, HW, acc);
        gather16(sB, rbase, c1 * CK, w, HW, o00, o01, o10, o11, w00, w01, w10, w11);

        // segment c1
        __syncthreads();
        consume16(sB, lbase, c1 * CK, w, HW, acc);
        if (c1 + 1 < NCH)
            gather16(sA, rbase, (c1 + 1) * CK, w, HW, o00, o01, o10, o11, w00, w01, w10, w11);

        // group boundary after every 4 chunks (c1 = 3, 7, 11, 15)
        if ((c1 & 3) == 3) {
            const int g = c1 >> 2;
            float* ob = out + (((size_t)(b * NGRP + g) * WIN) * HH + h) * WW + w;
#pragma unroll
            for (int k = 0; k < WIN; ++k)
                ob[(size_t)k * HW] = acc[k] * scale;
#pragma unroll
            for (int k = 0; k < WIN; ++k) acc[k] = 0.f;
        }
    }
}

extern "C" void kernel_launch(void* const* d_in, const int* in_sizes, int n_in,
                              void* d_out, int out_size)
{
    const float* left  = (const float*)d_in[0];
    const float* right = (const float*)d_in[1];
    const float* flow  = (const float*)d_in[2];
    float* out = (float*)d_out;

    dim3 grid(BB * HH);   // 512 blocks, one per (b, h) row
    dim3 block(WW);       // 256 threads, one per w
    crestereo_pipe_kernel<<<grid, block>>>(left, right, flow, out);
}

// round 14
// speedup vs baseline: 1.9583x; 1.9583x over previous
#include <cuda_runtime.h>

// Fixed problem shape
#define BB   4
#define CC   256
#define HH   128
#define WW   256
#define NGRP 4
#define CG   64      // channels per group
#define WIN  9       // window taps (1 x 9)
#define CK   32      // channel chunk held in smem
#define BAT  8       // channels per explicit load batch (32 LDGs in flight)
#define SRS  264     // padded smem row: pixel w at col w+4, replicate pad 4 each side

__global__ __launch_bounds__(256, 3)
void crestereo_batch_kernel(const float* __restrict__ left,
                            const float* __restrict__ right,
                            const float* __restrict__ flow,
                            float* __restrict__ out)
{
    __shared__ float srw[CK][SRS];

    const int bh = blockIdx.x;
    const int b  = bh >> 7;          // bh / HH
    const int h  = bh & (HH - 1);
    const int w  = threadIdx.x;
    const int HW = HH * WW;

    // ---- per-pixel bilinear setup (invariant across channels) ----
    const float fx = flow[(((size_t)b * 2 + 0) * HH + h) * WW + w];
    const float fy = flow[(((size_t)b * 2 + 1) * HH + h) * WW + w];
    const float x = (float)w + fx;
    const float y = (float)h + fy;
    const float x0f = floorf(x);
    const float y0f = floorf(y);
    const int ix0 = (int)x0f;
    const int iy0 = (int)y0f;
    const float ax = x - x0f;
    const float ay = y - y0f;

    float w00 = (1.f - ax) * (1.f - ay);
    float w01 = ax * (1.f - ay);
    float w10 = (1.f - ax) * ay;
    float w11 = ax * ay;

    const bool vx0 = (ix0     >= 0) & (ix0     <= WW - 1);
    const bool vx1 = (ix0 + 1 >= 0) & (ix0 + 1 <= WW - 1);
    const bool vy0 = (iy0     >= 0) & (iy0     <= HH - 1);
    const bool vy1 = (iy0 + 1 >= 0) & (iy0 + 1 <= HH - 1);
    if (!(vx0 & vy0)) w00 = 0.f;
    if (!(vx1 & vy0)) w01 = 0.f;
    if (!(vx0 & vy1)) w10 = 0.f;
    if (!(vx1 & vy1)) w11 = 0.f;

    const int x0c = min(max(ix0, 0), WW - 1);
    const int x1c = min(max(ix0 + 1, 0), WW - 1);
    const int y0c = min(max(iy0, 0), HH - 1);
    const int y1c = min(max(iy0 + 1, 0), HH - 1);

    const int o00 = y0c * WW + x0c;
    const int o01 = y0c * WW + x1c;
    const int o10 = y1c * WW + x0c;
    const int o11 = y1c * WW + x1c;

    const float* lbase = left  + (size_t)b * CC * HW + (size_t)h * WW + w;
    const float* rbase = right + (size_t)b * CC * HW;

    float acc[WIN];

    for (int g = 0; g < NGRP; ++g) {
#pragma unroll
        for (int k = 0; k < WIN; ++k) acc[k] = 0.f;

        for (int ch0 = g * CG; ch0 < (g + 1) * CG; ch0 += CK) {
            __syncthreads();   // protect previous chunk's readers

            // ---- phase 1: gather in explicit 8-channel batches ----
            // Each batch issues its 32 corner LDGs into registers BEFORE any
            // FMA/STS, guaranteeing deep MLP independent of ptxas heuristics.
#pragma unroll
            for (int cb = 0; cb < CK; cb += BAT) {
                float t[BAT][4];
#pragma unroll
                for (int j = 0; j < BAT; ++j) {
                    const float* rb = rbase + (size_t)(ch0 + cb + j) * HW;
                    t[j][0] = rb[o00];
                    t[j][1] = rb[o01];
                    t[j][2] = rb[o10];
                    t[j][3] = rb[o11];
                }
#pragma unroll
                for (int j = 0; j < BAT; ++j) {
                    float v = t[j][0] * w00;
                    v = fmaf(t[j][1], w01, v);
                    v = fmaf(t[j][2], w10, v);
                    v = fmaf(t[j][3], w11, v);
                    const int cc = cb + j;
                    srw[cc][4 + w] = v;
                    if (w == 0) {
                        srw[cc][0] = v; srw[cc][1] = v; srw[cc][2] = v; srw[cc][3] = v;
                    }
                    if (w == WW - 1) {
                        srw[cc][WW + 4] = v; srw[cc][WW + 5] = v;
                        srw[cc][WW + 6] = v; srw[cc][WW + 7] = v;
                    }
                }
            }
            __syncthreads();

            // ---- phase 2: 9-tap sliding-window accumulate (taps at sp[0..8]) ----
#pragma unroll
            for (int cc = 0; cc < CK; ++cc) {
                const float lv = lbase[(size_t)(ch0 + cc) * HW];
                const float* sp = &srw[cc][w];
#pragma unroll
                for (int k = 0; k < WIN; ++k)
                    acc[k] = fmaf(lv, sp[k], acc[k]);
            }
        }

        // ---- write 9 output taps for this group (coalesced across w) ----
        const float scale = 1.f / (float)CG;
        float* ob = out + (((size_t)(b * NGRP + g) * WIN) * HH + h) * WW + w;
#pragma unroll
        for (int k = 0; k < WIN; ++k)
            ob[(size_t)k * HW] = acc[k] * scale;
    }
}

extern "C" void kernel_launch(void* const* d_in, const int* in_sizes, int n_in,
                              void* d_out, int out_size)
{
    const float* left  = (const float*)d_in[0];
    const float* right = (const float*)d_in[1];
    const float* flow  = (const float*)d_in[2];
    float* out = (float*)d_out;

    dim3 grid(BB * HH);   // 512 blocks, one per (b, h) row
    dim3 block(WW);       // 256 threads, one per w
    crestereo_batch_kernel<<<grid, block>>>(left, right, flow, out);
}